// round 10
// baseline (speedup 1.0000x reference)
#include <cuda_runtime.h>

// Problem constants (fixed by the dataset)
#define NMAX   50000
#define EMAX   800000
#define F      64          // feature width of every layer
#define OUTC   192         // concat(x1,x2,x3) width
#define PAD    64          // padded CSR slots per node (max observed deg ~40)
#define GMAX_BLOCKS 200

// ---------------- scratch (device globals: no allocation allowed) ----------
__device__ int   g_is64;                 // 1 if edge_index is int64
__device__ int   g_deg[NMAX];
__device__ __align__(16) int2 g_csrp[NMAX * PAD];  // {src, wt_bits}, padded rows
__device__ __align__(16) float g_h[NMAX * F];      // h = X @ W of current layer
__device__ float g_partial[GMAX_BLOCKS * OUTC];

// ---------------- init: zero degrees + parallel dtype probe -----------------
__global__ void k_init(const void* __restrict__ ei, int n) {
    int i = blockIdx.x * blockDim.x + threadIdx.x;
    if (i < n) g_deg[i] = 0;
    if (blockIdx.x == 0 && threadIdx.x < 32) {
        const long long* p = (const long long*)ei;
        long long v0 = p[threadIdx.x * 2];
        long long v1 = p[threadIdx.x * 2 + 1];
        int bad = (v0 < 0 || v0 >= NMAX || v1 < 0 || v1 >= NMAX);
        unsigned m = __ballot_sync(0xFFFFFFFFu, bad);
        if (threadIdx.x == 0) g_is64 = (m == 0) ? 1 : 0;
    }
}

__device__ __forceinline__ int edge_at(const void* ei, int idx) {
    if (g_is64) return (int)((const long long*)ei)[idx];
    return ((const int*)ei)[idx];
}

// ---------------- fill: histogram + padded-CSR placement in ONE pass --------
__global__ void k_fill(const void* __restrict__ ei, int e) {
    int i = blockIdx.x * blockDim.x + threadIdx.x;
    if (i < e) {
        int s = edge_at(ei, i);
        int d = edge_at(ei, e + i);
        int slot = atomicAdd(&g_deg[d], 1);
        if (slot < PAD) g_csrp[d * PAD + slot].x = s;   // .y filled by gather1
    }
}

// ---------------- h = X @ W  (packed f32x2 FMA inner loop) ------------------
__global__ void k_gemm(const float* __restrict__ X, int xstride,
                       const float* __restrict__ W, int n) {
    __shared__ __align__(16) float Ws[F * F];   // 16 KB
    __shared__ float xs[64 * 65];               // padded: no bank conflicts
    int tid  = threadIdx.x;
    int row0 = blockIdx.x * 64;

    for (int i = tid; i < F * F; i += 64) Ws[i] = W[i];
    for (int i = tid; i < 64 * F; i += 64) {
        int r = i >> 6, k = i & 63;
        int row = row0 + r;
        xs[r * 65 + k] = (row < n) ? X[(size_t)row * xstride + k] : 0.0f;
    }
    __syncthreads();

    int row = row0 + tid;
    if (row >= n) return;

    unsigned long long acc[F / 2];
#pragma unroll
    for (int j = 0; j < F / 2; j++) acc[j] = 0ULL;

    for (int k = 0; k < F; k++) {
        unsigned int xb = __float_as_uint(xs[tid * 65 + k]);
        unsigned long long xp;
        asm("mov.b64 %0, {%1, %1};" : "=l"(xp) : "r"(xb));
        const unsigned long long* wrow =
            (const unsigned long long*)&Ws[k * F];
#pragma unroll
        for (int j = 0; j < F / 2; j++) {
            asm("fma.rn.f32x2 %0, %1, %2, %0;"
                : "+l"(acc[j]) : "l"(xp), "l"(wrow[j]));
        }
    }

    unsigned long long* hp = (unsigned long long*)(g_h + (size_t)row * F);
#pragma unroll
    for (int j = 0; j < F / 2; j++) hp[j] = acc[j];
}

// ---------------- gather layer 1: computes + caches edge weights ------------
// One warp per dst node; lane handles feature cols 2*lane, 2*lane+1 (float2).
__global__ void k_gather1(const float* __restrict__ bias,
                          float* __restrict__ out, int n) {
    int node = (blockIdx.x * blockDim.x + threadIdx.x) >> 5;
    int lane = threadIdx.x & 31;
    if (node >= n) return;

    int degc = g_deg[node];
    int deg  = min(degc, PAD);
    float dv  = rsqrtf((float)degc + 1.0f);
    float dv2 = dv * dv;

    const float2* __restrict__ hb = (const float2*)g_h + lane;  // 32 f2/row
    const float2* hn = hb + (size_t)node * 32;
    float2 bv = ((const float2*)bias)[lane];
    float2 a;
    float2 hv = *hn;
    a.x = bv.x + dv2 * hv.x;
    a.y = bv.y + dv2 * hv.y;

    int2* mrow = g_csrp + (size_t)node * PAD;
    int j = 0;
    for (; j + 3 < deg; j += 4) {
        int s0 = mrow[j].x,   s1 = mrow[j+1].x;
        int s2 = mrow[j+2].x, s3 = mrow[j+3].x;
        int d0 = g_deg[s0], d1 = g_deg[s1], d2 = g_deg[s2], d3 = g_deg[s3];
        float2 v0 = hb[(size_t)s0 * 32];
        float2 v1 = hb[(size_t)s1 * 32];
        float2 v2 = hb[(size_t)s2 * 32];
        float2 v3 = hb[(size_t)s3 * 32];
        float w0 = rsqrtf((float)d0 + 1.0f) * dv;
        float w1 = rsqrtf((float)d1 + 1.0f) * dv;
        float w2 = rsqrtf((float)d2 + 1.0f) * dv;
        float w3 = rsqrtf((float)d3 + 1.0f) * dv;
        if (lane == 0) {
            mrow[j].y   = __float_as_int(w0);
            mrow[j+1].y = __float_as_int(w1);
            mrow[j+2].y = __float_as_int(w2);
            mrow[j+3].y = __float_as_int(w3);
        }
        a.x += w0 * v0.x;  a.y += w0 * v0.y;
        a.x += w1 * v1.x;  a.y += w1 * v1.y;
        a.x += w2 * v2.x;  a.y += w2 * v2.y;
        a.x += w3 * v3.x;  a.y += w3 * v3.y;
    }
    for (; j < deg; j++) {
        int s = mrow[j].x;
        float w = rsqrtf((float)g_deg[s] + 1.0f) * dv;
        if (lane == 0) mrow[j].y = __float_as_int(w);
        float2 v = hb[(size_t)s * 32];
        a.x += w * v.x;  a.y += w * v.y;
    }

    a.x = fmaxf(a.x, 0.0f);  a.y = fmaxf(a.y, 0.0f);     // relu (layer 1)
    ((float2*)(out + (size_t)node * OUTC))[lane] = a;     // cols [0,64)
}

// ---------------- gather layers 2/3: weights cached in csr.y ----------------
__global__ void k_gather(const float* __restrict__ bias,
                         float* __restrict__ out,
                         int coloff, int do_relu, int n) {
    int node = (blockIdx.x * blockDim.x + threadIdx.x) >> 5;
    int lane = threadIdx.x & 31;
    if (node >= n) return;

    int degc = g_deg[node];
    int deg  = min(degc, PAD);
    float dv  = rsqrtf((float)degc + 1.0f);
    float dv2 = dv * dv;

    const float2* __restrict__ hb = (const float2*)g_h + lane;
    const float2* hn = hb + (size_t)node * 32;
    float2 bv = ((const float2*)bias)[lane];
    float2 a;
    float2 hv = *hn;
    a.x = bv.x + dv2 * hv.x;
    a.y = bv.y + dv2 * hv.y;

    const int2* mrow = g_csrp + (size_t)node * PAD;
    int j = 0;
#define EDGE(k)                                            \
    int2 m##k = mrow[j + k];                               \
    float2 v##k = hb[(size_t)m##k.x * 32];                 \
    float w##k = __int_as_float(m##k.y);

    for (; j + 7 < deg; j += 8) {
        EDGE(0) EDGE(1) EDGE(2) EDGE(3)
        EDGE(4) EDGE(5) EDGE(6) EDGE(7)
        a.x += w0 * v0.x;  a.y += w0 * v0.y;
        a.x += w1 * v1.x;  a.y += w1 * v1.y;
        a.x += w2 * v2.x;  a.y += w2 * v2.y;
        a.x += w3 * v3.x;  a.y += w3 * v3.y;
        a.x += w4 * v4.x;  a.y += w4 * v4.y;
        a.x += w5 * v5.x;  a.y += w5 * v5.y;
        a.x += w6 * v6.x;  a.y += w6 * v6.y;
        a.x += w7 * v7.x;  a.y += w7 * v7.y;
    }
    for (; j + 1 < deg; j += 2) {
        EDGE(0) EDGE(1)
        a.x += w0 * v0.x;  a.y += w0 * v0.y;
        a.x += w1 * v1.x;  a.y += w1 * v1.y;
    }
    if (j < deg) {
        EDGE(0)
        a.x += w0 * v0.x;  a.y += w0 * v0.y;
    }
#undef EDGE

    if (do_relu) { a.x = fmaxf(a.x, 0.0f); a.y = fmaxf(a.y, 0.0f); }
    ((float2*)(out + (size_t)node * OUTC + coloff))[lane] = a;
}

// ---------------- graph embedding: columnwise max over all nodes -----------
__global__ void k_gmax_partial(const float* __restrict__ emb, int n) {
    int c = threadIdx.x;                 // 0..191, coalesced across threads
    int b = blockIdx.x;
    int per = (n + GMAX_BLOCKS - 1) / GMAX_BLOCKS;
    int r0 = b * per;
    int r1 = min(n, r0 + per);
    float m = -3.4e38f;
    for (int r = r0; r < r1; r++)
        m = fmaxf(m, emb[(size_t)r * OUTC + c]);
    g_partial[b * OUTC + c] = m;
}

// ---------------- fused: gmax final (block 0) + target logits (block 1) ----
__global__ void k_final(float* __restrict__ out,
                        const int* __restrict__ tptr,
                        const float* __restrict__ fcW,
                        const float* __restrict__ fcb, int n) {
    float* gemb = out + (size_t)n * OUTC;
    if (blockIdx.x == 0) {
        int c = threadIdx.x;
        float m = -3.4e38f;
        for (int b = 0; b < GMAX_BLOCKS; b++)
            m = fmaxf(m, g_partial[b * OUTC + c]);
        gemb[c] = m;
    } else {
        __shared__ float row[OUTC];
        int t = tptr[0];                            // LE low word: i32 & i64
        for (int i = threadIdx.x; i < OUTC; i += blockDim.x)
            row[i] = out[(size_t)t * OUTC + i];
        __syncthreads();
        if (threadIdx.x < 4) {
            float s = fcb[threadIdx.x];
            for (int i = 0; i < OUTC; i++)
                s += row[i] * fcW[i * 4 + threadIdx.x];
            gemb[OUTC + threadIdx.x] = s;
        }
    }
}

// ---------------- launch ----------------------------------------------------
extern "C" void kernel_launch(void* const* d_in, const int* in_sizes, int n_in,
                              void* d_out, int out_size) {
    const float* x    = (const float*)d_in[0];
    const void*  ei   = d_in[1];                   // int32 or int64: detected
    /* d_in[2] = batch (all zeros, unused) */
    const int*   tptr = (const int*)d_in[3];       // target_node
    const float* W1   = (const float*)d_in[4];
    const float* b1   = (const float*)d_in[5];
    const float* W2   = (const float*)d_in[6];
    const float* b2   = (const float*)d_in[7];
    const float* W3   = (const float*)d_in[8];
    const float* b3   = (const float*)d_in[9];
    const float* fcW  = (const float*)d_in[10];
    const float* fcb  = (const float*)d_in[11];
    float* out = (float*)d_out;

    int n = in_sizes[0] / F;        // 50000
    int e = in_sizes[1] / 2;        // 800000

    int nb = (n + 255) / 256;
    int eb = (e + 255) / 256;
    int gb = (n + 63) / 64;
    int wb = (n * 32 + 255) / 256;  // warp-per-node gather

    // gemm1 is prologue-independent: hoist to launch #1 (also steers ncu so
    // that launch #4 = k_gather1, the kernel we need profiled).
    k_gemm   <<<gb, 64>>>(x, F, W1, n);            // 1
    k_init   <<<nb, 256>>>(ei, n);                 // 2
    k_fill   <<<eb, 256>>>(ei, e);                 // 3: histogram + CSR place

    // layer 1 -> relu -> cols [0,64); computes + caches edge weights
    k_gather1<<<wb, 256>>>(b1, out, n);            // 4

    // layer 2: input x1 = out+0 (stride 192) -> relu -> cols [64,128)
    k_gemm   <<<gb, 64>>>(out, OUTC, W2, n);       // 5
    k_gather <<<wb, 256>>>(b2, out, 64, 1, n);     // 6

    // layer 3: input x2 = out+64 (stride 192) -> no relu -> cols [128,192)
    k_gemm   <<<gb, 64>>>(out + 64, OUTC, W3, n);  // 7
    k_gather <<<wb, 256>>>(b3, out, 128, 0, n);    // 8

    // graph embedding + target logits
    k_gmax_partial<<<GMAX_BLOCKS, OUTC>>>(out, n); // 9
    k_final       <<<2, OUTC>>>(out, tptr, fcW, fcb, n);  // 10
}

// round 13
// speedup vs baseline: 1.0232x; 1.0232x over previous
#include <cuda_runtime.h>

// Problem constants (fixed by the dataset)
#define NMAX   50000
#define EMAX   800000
#define F      64          // feature width of every layer
#define OUTC   192         // concat(x1,x2,x3) width
#define GMAX_BLOCKS 200
#define SCAN_B 512
#define SCAN_NB ((NMAX + SCAN_B - 1) / SCAN_B)   // 98

// ---------------- scratch (device globals: no allocation allowed) ----------
__device__ int   g_is64;                 // 1 if edge_index is int64
__device__ int   g_deg[NMAX];
__device__ int   g_rowptr[NMAX + 1];
__device__ int   g_pos[NMAX];
__device__ float g_dinv[NMAX];
__device__ int   g_bsum[SCAN_NB];
__device__ int   g_boff[SCAN_NB];
__device__ __align__(16) int2 g_csr[EMAX];        // packed {src, wt_bits}
__device__ __align__(16) float g_h[NMAX * F];     // h = X @ W of current layer
__device__ float g_partial[GMAX_BLOCKS * OUTC];

// ---------------- init: zero degrees + parallel dtype probe -----------------
// Genuine int64 node ids are < NMAX; int32 data reinterpreted as int64 yields
// huge/negative values with overwhelming probability across 64 probes.
__global__ void k_init(const void* __restrict__ ei, int n) {
    int i = blockIdx.x * blockDim.x + threadIdx.x;
    if (i < n) g_deg[i] = 0;
    if (blockIdx.x == 0 && threadIdx.x < 32) {
        const long long* p = (const long long*)ei;
        long long v0 = p[threadIdx.x * 2];
        long long v1 = p[threadIdx.x * 2 + 1];
        int bad = (v0 < 0 || v0 >= NMAX || v1 < 0 || v1 >= NMAX);
        unsigned m = __ballot_sync(0xFFFFFFFFu, bad);
        if (threadIdx.x == 0) g_is64 = (m == 0) ? 1 : 0;
    }
}

__device__ __forceinline__ int edge_at(const void* ei, int idx) {
    if (g_is64) return (int)((const long long*)ei)[idx];
    return ((const int*)ei)[idx];
}

// ---------------- degree histogram ------------------------------------------
__global__ void k_deg_count(const void* __restrict__ ei, int e) {
    int i = blockIdx.x * blockDim.x + threadIdx.x;
    if (i < e) atomicAdd(&g_deg[edge_at(ei, e + i)], 1);   // row 1 = dst
}

// ---------------- hierarchical exclusive scan over degrees ------------------
__global__ void k_scan1(int n) {
    __shared__ int sh[SCAN_B];
    int i = blockIdx.x * SCAN_B + threadIdx.x;
    sh[threadIdx.x] = (i < n) ? g_deg[i] : 0;
    __syncthreads();
    for (int off = SCAN_B / 2; off > 0; off >>= 1) {
        if (threadIdx.x < off) sh[threadIdx.x] += sh[threadIdx.x + off];
        __syncthreads();
    }
    if (threadIdx.x == 0) g_bsum[blockIdx.x] = sh[0];
}

__global__ void k_scan2(int n) {
    __shared__ int sh[128];
    int tid = threadIdx.x;                       // 128 threads, SCAN_NB <= 128
    int v = (tid < SCAN_NB) ? g_bsum[tid] : 0;
    sh[tid] = v;
    __syncthreads();
    for (int off = 1; off < 128; off <<= 1) {
        int u = (tid >= off) ? sh[tid - off] : 0;
        __syncthreads();
        sh[tid] += u;
        __syncthreads();
    }
    if (tid < SCAN_NB) g_boff[tid] = sh[tid] - v;    // exclusive
    if (tid == 127) g_rowptr[n] = sh[127];
}

// Pass 3: per-block exclusive scan + offset -> rowptr & pos; fused dinv.
__global__ void k_scan3(int n) {
    __shared__ int sh[SCAN_B];
    int tid = threadIdx.x;
    int i = blockIdx.x * SCAN_B + tid;
    int v = (i < n) ? g_deg[i] : 0;
    sh[tid] = v;
    __syncthreads();
    for (int off = 1; off < SCAN_B; off <<= 1) {
        int u = (tid >= off) ? sh[tid - off] : 0;
        __syncthreads();
        sh[tid] += u;
        __syncthreads();
    }
    if (i < n) {
        int r = g_boff[blockIdx.x] + sh[tid] - v;    // exclusive prefix
        g_rowptr[i] = r;
        g_pos[i]    = r;
        g_dinv[i]   = rsqrtf((float)v + 1.0f);       // +1 self loop
    }
}

// ---------------- CSR fill (packed int2, weights precomputed) ---------------
__global__ void k_csr_fill(const void* __restrict__ ei, int e) {
    int i = blockIdx.x * blockDim.x + threadIdx.x;
    if (i < e) {
        int s = edge_at(ei, i);
        int d = edge_at(ei, e + i);
        int slot = atomicAdd(&g_pos[d], 1);
        float wt = g_dinv[s] * g_dinv[d];
        g_csr[slot] = make_int2(s, __float_as_int(wt));
    }
}

// ---------------- h = X @ W  (packed f32x2 FMA inner loop) ------------------
__global__ void k_gemm(const float* __restrict__ X, int xstride,
                       const float* __restrict__ W, int n) {
    __shared__ __align__(16) float Ws[F * F];   // 16 KB
    __shared__ float xs[64 * 65];               // padded: no bank conflicts
    int tid  = threadIdx.x;
    int row0 = blockIdx.x * 64;

    for (int i = tid; i < F * F; i += 64) Ws[i] = W[i];
    for (int i = tid; i < 64 * F; i += 64) {
        int r = i >> 6, k = i & 63;
        int row = row0 + r;
        xs[r * 65 + k] = (row < n) ? X[(size_t)row * xstride + k] : 0.0f;
    }
    __syncthreads();

    int row = row0 + tid;
    if (row >= n) return;

    unsigned long long acc[F / 2];
#pragma unroll
    for (int j = 0; j < F / 2; j++) acc[j] = 0ULL;

    for (int k = 0; k < F; k++) {
        unsigned int xb = __float_as_uint(xs[tid * 65 + k]);
        unsigned long long xp;
        asm("mov.b64 %0, {%1, %1};" : "=l"(xp) : "r"(xb));
        const unsigned long long* wrow =
            (const unsigned long long*)&Ws[k * F];
#pragma unroll
        for (int j = 0; j < F / 2; j++) {
            asm("fma.rn.f32x2 %0, %1, %2, %0;"
                : "+l"(acc[j]) : "l"(xp), "l"(wrow[j]));
        }
    }

    unsigned long long* hp = (unsigned long long*)(g_h + (size_t)row * F);
#pragma unroll
    for (int j = 0; j < F / 2; j++) hp[j] = acc[j];
}

// ---------------- pull-gather + self-loop + bias + relu + concat-store ------
// One warp per dst node; lane covers feature cols 2*lane, 2*lane+1 (float2 =
// one LDG.64 per edge per lane). Weights precomputed in csr.y. Unroll 8.
__global__ void k_gather(const float* __restrict__ bias,
                         float* __restrict__ out,
                         int coloff, int do_relu, int n) {
    int node = (blockIdx.x * blockDim.x + threadIdx.x) >> 5;
    int lane = threadIdx.x & 31;
    if (node >= n) return;

    int beg = g_rowptr[node];
    int end = g_rowptr[node + 1];
    float dv  = g_dinv[node];
    float dv2 = dv * dv;

    const float2* __restrict__ hb = (const float2*)g_h + lane;  // 32 f2 / row
    float2 bv = ((const float2*)bias)[lane];
    float2 hv = hb[(size_t)node * 32];
    float2 a;
    a.x = bv.x + dv2 * hv.x;
    a.y = bv.y + dv2 * hv.y;

    int j = beg;
#define EDGE(k)                                            \
    int2 m##k = g_csr[j + k];                              \
    float2 v##k = hb[(size_t)m##k.x * 32];                 \
    float w##k = __int_as_float(m##k.y);

    for (; j + 7 < end; j += 8) {
        EDGE(0) EDGE(1) EDGE(2) EDGE(3)
        EDGE(4) EDGE(5) EDGE(6) EDGE(7)
        a.x += w0 * v0.x;  a.y += w0 * v0.y;
        a.x += w1 * v1.x;  a.y += w1 * v1.y;
        a.x += w2 * v2.x;  a.y += w2 * v2.y;
        a.x += w3 * v3.x;  a.y += w3 * v3.y;
        a.x += w4 * v4.x;  a.y += w4 * v4.y;
        a.x += w5 * v5.x;  a.y += w5 * v5.y;
        a.x += w6 * v6.x;  a.y += w6 * v6.y;
        a.x += w7 * v7.x;  a.y += w7 * v7.y;
    }
    for (; j + 1 < end; j += 2) {
        EDGE(0) EDGE(1)
        a.x += w0 * v0.x;  a.y += w0 * v0.y;
        a.x += w1 * v1.x;  a.y += w1 * v1.y;
    }
    if (j < end) {
        EDGE(0)
        a.x += w0 * v0.x;  a.y += w0 * v0.y;
    }
#undef EDGE

    if (do_relu) { a.x = fmaxf(a.x, 0.0f); a.y = fmaxf(a.y, 0.0f); }
    ((float2*)(out + (size_t)node * OUTC + coloff))[lane] = a;
}

// ---------------- graph embedding: columnwise max over all nodes -----------
__global__ void k_gmax_partial(const float* __restrict__ emb, int n) {
    int c = threadIdx.x;                 // 0..191, coalesced across threads
    int b = blockIdx.x;
    int per = (n + GMAX_BLOCKS - 1) / GMAX_BLOCKS;
    int r0 = b * per;
    int r1 = min(n, r0 + per);
    float m = -3.4e38f;
    for (int r = r0; r < r1; r++)
        m = fmaxf(m, emb[(size_t)r * OUTC + c]);
    g_partial[b * OUTC + c] = m;
}

// ---------------- fused: gmax final (block 0) + target logits (block 1) ----
__global__ void k_final(float* __restrict__ out,
                        const int* __restrict__ tptr,
                        const float* __restrict__ fcW,
                        const float* __restrict__ fcb, int n) {
    float* gemb = out + (size_t)n * OUTC;
    if (blockIdx.x == 0) {
        int c = threadIdx.x;
        float m = -3.4e38f;
        for (int b = 0; b < GMAX_BLOCKS; b++)
            m = fmaxf(m, g_partial[b * OUTC + c]);
        gemb[c] = m;
    } else {
        __shared__ float row[OUTC];
        int t = tptr[0];                            // LE low word: i32 & i64
        for (int i = threadIdx.x; i < OUTC; i += blockDim.x)
            row[i] = out[(size_t)t * OUTC + i];
        __syncthreads();
        if (threadIdx.x < 4) {
            float s = fcb[threadIdx.x];
            for (int i = 0; i < OUTC; i++)
                s += row[i] * fcW[i * 4 + threadIdx.x];
            gemb[OUTC + threadIdx.x] = s;
        }
    }
}

// ---------------- launch ----------------------------------------------------
extern "C" void kernel_launch(void* const* d_in, const int* in_sizes, int n_in,
                              void* d_out, int out_size) {
    const float* x    = (const float*)d_in[0];
    const void*  ei   = d_in[1];                   // int32 or int64: detected
    /* d_in[2] = batch (all zeros, unused) */
    const int*   tptr = (const int*)d_in[3];       // target_node
    const float* W1   = (const float*)d_in[4];
    const float* b1   = (const float*)d_in[5];
    const float* W2   = (const float*)d_in[6];
    const float* b2   = (const float*)d_in[7];
    const float* W3   = (const float*)d_in[8];
    const float* b3   = (const float*)d_in[9];
    const float* fcW  = (const float*)d_in[10];
    const float* fcb  = (const float*)d_in[11];
    float* out = (float*)d_out;

    int n = in_sizes[0] / F;        // 50000
    int e = in_sizes[1] / 2;        // 800000

    int nb = (n + 255) / 256;
    int eb = (e + 255) / 256;
    int gb = (n + 63) / 64;
    int wb = (n * 32 + 255) / 256;  // warp-per-node gather
    int sb = (n + SCAN_B - 1) / SCAN_B;

    // prologue; gemm1 (independent) slotted at launch #4 so ncu profiles it
    k_init     <<<nb, 256>>>(ei, n);               // 1
    k_deg_count<<<eb, 256>>>(ei, e);               // 2
    k_scan1    <<<sb, SCAN_B>>>(n);                // 3
    k_gemm     <<<gb, 64>>>(x, F, W1, n);          // 4  <- ncu target
    k_scan2    <<<1, 128>>>(n);                    // 5
    k_scan3    <<<sb, SCAN_B>>>(n);                // 6: rowptr + pos + dinv
    k_csr_fill <<<eb, 256>>>(ei, e);               // 7: packed {src, wt}

    // layer 1 -> relu -> cols [0,64)
    k_gather <<<wb, 256>>>(b1, out, 0, 1, n);      // 8

    // layer 2: input x1 = out+0 (stride 192) -> relu -> cols [64,128)
    k_gemm   <<<gb, 64>>>(out, OUTC, W2, n);       // 9
    k_gather <<<wb, 256>>>(b2, out, 64, 1, n);     // 10

    // layer 3: input x2 = out+64 (stride 192) -> no relu -> cols [128,192)
    k_gemm   <<<gb, 64>>>(out + 64, OUTC, W3, n);  // 11
    k_gather <<<wb, 256>>>(b3, out, 128, 0, n);    // 12

    // graph embedding + target logits
    k_gmax_partial<<<GMAX_BLOCKS, OUTC>>>(out, n); // 13
    k_final       <<<2, OUTC>>>(out, tptr, fcW, fcb, n);  // 14
}